// round 3
// baseline (speedup 1.0000x reference)
#include <cuda_runtime.h>
#include <cstdint>

// GENConv fused: gather + relu + softmax_sg aggregation + linear.
//
// Strategy (round 3): eliminate the 410MB float-atomic traffic (LTS-atomic
// floor ~60us) by building a dst-CSR each call, then doing a per-node gather:
//   1. count_kernel : deg[dst]++            (800k int atomics, spread)
//   2. scan_kernel  : start = exclusive_scan(deg)   (1 block)
//   3. fill_kernel  : esrc[slot] = src      (atomic slot allocation)
//   4. node_kernel  : warp per node; s,t accumulated in registers over the
//                     node's edge list; h = t/s written directly (no atomics)
//   5. gemm_kernel  : out = h @ W^T + b
// Softmax logits are bounded (relu(x)+eps, beta=1) -> no max-subtraction.

#define EPS 1e-7f

constexpr int MAX_N = 50000;
constexpr int MAX_E = 800000;
constexpr int D     = 64;
constexpr int SCAN_T = 1024;

__device__ int   g_deg[MAX_N];
__device__ int   g_start[MAX_N];
__device__ int   g_cursor[MAX_N];
__device__ int   g_esrc[MAX_E];
__device__ float g_h[(size_t)MAX_N * D];

__global__ void __launch_bounds__(256)
count_kernel(const int* __restrict__ ei, int E)
{
    int e = blockIdx.x * blockDim.x + threadIdx.x;
    if (e < E) atomicAdd(&g_deg[__ldg(ei + e)], 1);
}

// Single-block exclusive scan over N degree counts (N ~ 50k, chunked serial +
// Hillis-Steele over 1024 partials). Writes start[] and cursor[] copies.
__global__ void __launch_bounds__(SCAN_T)
scan_kernel(int N)
{
    __shared__ int partial[SCAN_T];
    int t = threadIdx.x;
    int chunk = (N + SCAN_T - 1) / SCAN_T;
    int lo = t * chunk;
    int hi = min(lo + chunk, N);

    int sum = 0;
    for (int i = lo; i < hi; i++) sum += g_deg[i];
    partial[t] = sum;
    __syncthreads();

    for (int off = 1; off < SCAN_T; off <<= 1) {
        int v = partial[t];
        int o = (t >= off) ? partial[t - off] : 0;
        __syncthreads();
        partial[t] = v + o;
        __syncthreads();
    }
    int run = (t > 0) ? partial[t - 1] : 0;  // exclusive base for this chunk

    for (int i = lo; i < hi; i++) {
        g_start[i]  = run;
        g_cursor[i] = run;
        run += g_deg[i];
    }
}

__global__ void __launch_bounds__(256)
fill_kernel(const int* __restrict__ ei, int E)
{
    int e = blockIdx.x * blockDim.x + threadIdx.x;
    if (e < E) {
        int dst = __ldg(ei + e);
        int src = __ldg(ei + E + e);
        int pos = atomicAdd(&g_cursor[dst], 1);
        g_esrc[pos] = src;
    }
}

// One warp per node. Lane owns features (2*lane, 2*lane+1).
// Per edge: broadcast-load src id, coalesced float2 load of x row,
// accumulate s,t in registers. Epilogue: h = t/s (0 for empty segments).
__global__ void __launch_bounds__(256)
node_kernel(const float* __restrict__ x,
            const float* __restrict__ beta_p,
            int N)
{
    int warp = blockIdx.x * 8 + (threadIdx.x >> 5);
    if (warp >= N) return;
    int lane = threadIdx.x & 31;

    float beta = __ldg(beta_p);
    int beg = g_start[warp];
    int cnt = g_deg[warp];
    int end = beg + cnt;

    float s0 = 0.f, s1 = 0.f, t0 = 0.f, t1 = 0.f;

    int k = beg;
    // unrolled-by-2 main loop for MLP within the warp
    for (; k + 1 < end; k += 2) {
        int srcA = __ldg(g_esrc + k);
        int srcB = __ldg(g_esrc + k + 1);
        float2 xa = __ldg(reinterpret_cast<const float2*>(x + (size_t)srcA * D) + lane);
        float2 xb = __ldg(reinterpret_cast<const float2*>(x + (size_t)srcB * D) + lane);

        float ma0 = fmaxf(xa.x, 0.f) + EPS, ma1 = fmaxf(xa.y, 0.f) + EPS;
        float mb0 = fmaxf(xb.x, 0.f) + EPS, mb1 = fmaxf(xb.y, 0.f) + EPS;
        float ea0 = __expf(beta * ma0), ea1 = __expf(beta * ma1);
        float eb0 = __expf(beta * mb0), eb1 = __expf(beta * mb1);

        s0 += ea0 + eb0;           s1 += ea1 + eb1;
        t0 += ma0 * ea0 + mb0 * eb0; t1 += ma1 * ea1 + mb1 * eb1;
    }
    if (k < end) {
        int src = __ldg(g_esrc + k);
        float2 xv = __ldg(reinterpret_cast<const float2*>(x + (size_t)src * D) + lane);
        float m0 = fmaxf(xv.x, 0.f) + EPS, m1 = fmaxf(xv.y, 0.f) + EPS;
        float e0 = __expf(beta * m0), e1 = __expf(beta * m1);
        s0 += e0; s1 += e1; t0 += m0 * e0; t1 += m1 * e1;
    }

    float2 h;
    h.x = (cnt > 0) ? __fdividef(t0, s0) : 0.f;
    h.y = (cnt > 0) ? __fdividef(t1, s1) : 0.f;
    *(reinterpret_cast<float2*>(g_h + (size_t)warp * D) + lane) = h;
}

// out[n][j] = b[j] + sum_d h[n][d] * W[j][d]
// Block 256 = (j = tid&63) x (nl = tid>>6). 16-node tiles, prefetched;
// W rows in registers; 4 interleaved accumulator chains.
__global__ void __launch_bounds__(256)
gemm_kernel(const float* __restrict__ hA,
            const float* __restrict__ W,
            const float* __restrict__ bvec,
            float*       __restrict__ out,
            int N)
{
    __shared__ float hs[16][D];

    int j  = threadIdx.x & 63;
    int nl = threadIdx.x >> 6;

    float4 w[16];
    const float4* Wr = reinterpret_cast<const float4*>(W + (size_t)j * D);
    #pragma unroll
    for (int k = 0; k < 16; k++) w[k] = __ldg(Wr + k);
    float bj = __ldg(bvec + j);

    int ntiles = (N + 15) >> 4;
    float hv[4];
    int tile = blockIdx.x;

    if (tile < ntiles) {
        #pragma unroll
        for (int i = 0; i < 4; i++) {
            int n = (tile << 4) + nl + (i << 2);
            hv[i] = (n < N) ? __ldg(hA + (size_t)n * D + j) : 0.f;
        }
    }

    while (tile < ntiles) {
        __syncthreads();           // previous tile's readers done
        #pragma unroll
        for (int i = 0; i < 4; i++)
            hs[nl + (i << 2)][j] = hv[i];
        __syncthreads();           // tile staged

        int next = tile + gridDim.x;
        if (next < ntiles) {       // prefetch next tile (overlaps compute)
            #pragma unroll
            for (int i = 0; i < 4; i++) {
                int n = (next << 4) + nl + (i << 2);
                hv[i] = (n < N) ? __ldg(hA + (size_t)n * D + j) : 0.f;
            }
        }

        float acc0 = bj, acc1 = bj, acc2 = bj, acc3 = bj;
        const float4* h0 = reinterpret_cast<const float4*>(hs[nl]);
        const float4* h1 = reinterpret_cast<const float4*>(hs[nl + 4]);
        const float4* h2 = reinterpret_cast<const float4*>(hs[nl + 8]);
        const float4* h3 = reinterpret_cast<const float4*>(hs[nl + 12]);
        #pragma unroll
        for (int k = 0; k < 16; k++) {
            float4 a = h0[k], b = h1[k], c = h2[k], d = h3[k];
            acc0 = fmaf(a.x, w[k].x, acc0); acc1 = fmaf(b.x, w[k].x, acc1);
            acc2 = fmaf(c.x, w[k].x, acc2); acc3 = fmaf(d.x, w[k].x, acc3);
            acc0 = fmaf(a.y, w[k].y, acc0); acc1 = fmaf(b.y, w[k].y, acc1);
            acc2 = fmaf(c.y, w[k].y, acc2); acc3 = fmaf(d.y, w[k].y, acc3);
            acc0 = fmaf(a.z, w[k].z, acc0); acc1 = fmaf(b.z, w[k].z, acc1);
            acc2 = fmaf(c.z, w[k].z, acc2); acc3 = fmaf(d.z, w[k].z, acc3);
            acc0 = fmaf(a.w, w[k].w, acc0); acc1 = fmaf(b.w, w[k].w, acc1);
            acc2 = fmaf(c.w, w[k].w, acc2); acc3 = fmaf(d.w, w[k].w, acc3);
        }

        int nb = tile << 4;
        if (nb + nl      < N) out[(size_t)(nb + nl     ) * D + j] = acc0;
        if (nb + nl + 4  < N) out[(size_t)(nb + nl + 4 ) * D + j] = acc1;
        if (nb + nl + 8  < N) out[(size_t)(nb + nl + 8 ) * D + j] = acc2;
        if (nb + nl + 12 < N) out[(size_t)(nb + nl + 12) * D + j] = acc3;

        tile = next;
    }
}

extern "C" void kernel_launch(void* const* d_in, const int* in_sizes, int n_in,
                              void* d_out, int out_size)
{
    const float* x    = (const float*)d_in[0];   // [N, 64]
    const float* W    = (const float*)d_in[1];   // [64, 64]
    const float* bvec = (const float*)d_in[2];   // [64]
    const float* beta = (const float*)d_in[3];   // [1]
    const int*   ei   = (const int*)  d_in[4];   // [2, E]

    int N = in_sizes[0] / D;
    int E = in_sizes[4] / 2;
    float* out = (float*)d_out;

    void* degp = nullptr;
    cudaGetSymbolAddress(&degp, g_deg);
    cudaMemsetAsync(degp, 0, (size_t)N * sizeof(int));

    int eb = (E + 255) / 256;
    count_kernel<<<eb, 256>>>(ei, E);
    scan_kernel<<<1, SCAN_T>>>(N);
    fill_kernel<<<eb, 256>>>(ei, E);

    node_kernel<<<(N + 7) / 8, 256>>>(x, beta, N);

    void* hp = nullptr;
    cudaGetSymbolAddress(&hp, g_h);
    gemm_kernel<<<592, 256>>>((const float*)hp, W, bvec, out, N);
}

// round 4
// speedup vs baseline: 1.6554x; 1.6554x over previous
#include <cuda_runtime.h>
#include <cstdint>

// GENConv fused: gather + relu + softmax_sg aggregation + linear.
//
// Pass A (edge_kernel): s[n,d] += exp(beta*m), t[n,d] += m*exp(beta*m)
//   via red.global.add.v4.f32 (logits bounded -> no max-subtraction needed).
// Pass B (gemm_kernel): register-tiled SGEMM. h = t/s computed during the
//   smem staging (transposed, padded stride 68). Thread computes a 4x4
//   register tile; inner loop per d = 2x LDS.128 + 16 FFMA.

#define EPS 1e-7f

constexpr int MAX_N = 50000;
constexpr int D     = 64;
constexpr int TPAD  = 68;   // padded smem row stride (floats); 68*4B % 16B == 0

__device__ float g_s[(size_t)MAX_N * D];
__device__ float g_t[(size_t)MAX_N * D];

__device__ __forceinline__ void red_add_v4(float* p, float a, float b, float c, float d) {
    asm volatile("red.global.add.v4.f32 [%0], {%1, %2, %3, %4};"
                 :: "l"(p), "f"(a), "f"(b), "f"(c), "f"(d)
                 : "memory");
}

__global__ void __launch_bounds__(256)
edge_kernel(const float* __restrict__ x,
            const int*   __restrict__ ei,     // [2, E]: row0 = dst, row1 = src
            const float* __restrict__ beta_p,
            int E)
{
    int tid = blockIdx.x * blockDim.x + threadIdx.x;
    int e = tid >> 4;          // edge id
    if (e >= E) return;
    int q = tid & 15;          // which float4 of the 64-wide row

    float beta = __ldg(beta_p);
    int dst = __ldg(ei + e);
    int src = __ldg(ei + E + e);

    float4 xv = __ldg(reinterpret_cast<const float4*>(x + (size_t)src * D) + q);

    float m0 = fmaxf(xv.x, 0.f) + EPS;
    float m1 = fmaxf(xv.y, 0.f) + EPS;
    float m2 = fmaxf(xv.z, 0.f) + EPS;
    float m3 = fmaxf(xv.w, 0.f) + EPS;

    float e0 = __expf(beta * m0);
    float e1 = __expf(beta * m1);
    float e2 = __expf(beta * m2);
    float e3 = __expf(beta * m3);

    size_t off = (size_t)dst * D + (q << 2);
    red_add_v4(g_s + off, e0, e1, e2, e3);
    red_add_v4(g_t + off, m0 * e0, m1 * e1, m2 * e2, m3 * e3);
}

// out[n][j] = b[j] + sum_d (t[n][d]/s[n][d]) * W[j][d]
// Block = 256 threads, one 64-node x 64-feature tile.
// Stage: Wt[d][j] = W[j][d], hT[d][n] = t/s (transposed, padded).
// Compute: thread (tx, ty) owns nodes 4ty..4ty+3 x features 4tx..4tx+3.
__global__ void __launch_bounds__(256)
gemm_kernel(const float* __restrict__ sA,
            const float* __restrict__ tA,
            const float* __restrict__ W,
            const float* __restrict__ bvec,
            float*       __restrict__ out,
            int N)
{
    __shared__ float Wt[D * TPAD];
    __shared__ float hT[D * TPAD];

    int tid = threadIdx.x;
    int g   = tid >> 2;       // 0..63 : row (j for W stage, local node for h stage)
    int q   = tid & 3;        // 0..3  : quad group

    // ---- stage W transposed (once per block) ----
    {
        const float4* Wr = reinterpret_cast<const float4*>(W + (size_t)g * D);
        #pragma unroll
        for (int i = 0; i < 4; i++) {
            int dq = q + (i << 2);            // float4 index 0..15
            float4 w4 = __ldg(Wr + dq);
            int d = dq << 2;
            Wt[(d + 0) * TPAD + g] = w4.x;
            Wt[(d + 1) * TPAD + g] = w4.y;
            Wt[(d + 2) * TPAD + g] = w4.z;
            Wt[(d + 3) * TPAD + g] = w4.w;
        }
    }

    // ---- stage h = t/s transposed ----
    int tile0 = blockIdx.x << 6;
    {
        int n = tile0 + g;
        bool ok = n < N;
        size_t base = (size_t)(ok ? n : 0) * D;
        const float4* srow = reinterpret_cast<const float4*>(sA + base);
        const float4* trow = reinterpret_cast<const float4*>(tA + base);
        #pragma unroll
        for (int i = 0; i < 4; i++) {
            int dq = q + (i << 2);
            float4 sv = __ldg(srow + dq);
            float4 tv = __ldg(trow + dq);
            int d = dq << 2;
            float h0 = (ok && sv.x > 0.f) ? __fdividef(tv.x, sv.x) : 0.f;
            float h1 = (ok && sv.y > 0.f) ? __fdividef(tv.y, sv.y) : 0.f;
            float h2 = (ok && sv.z > 0.f) ? __fdividef(tv.z, sv.z) : 0.f;
            float h3 = (ok && sv.w > 0.f) ? __fdividef(tv.w, sv.w) : 0.f;
            hT[(d + 0) * TPAD + g] = h0;
            hT[(d + 1) * TPAD + g] = h1;
            hT[(d + 2) * TPAD + g] = h2;
            hT[(d + 3) * TPAD + g] = h3;
        }
    }
    __syncthreads();

    // ---- compute 4x4 register tile ----
    int tx = tid & 15;        // feature group: j = 4*tx..4*tx+3
    int ty = tid >> 4;        // node group:    n = 4*ty..4*ty+3

    float4 bv = __ldg(reinterpret_cast<const float4*>(bvec) + tx);
    float acc[4][4];
    #pragma unroll
    for (int i = 0; i < 4; i++) {
        acc[i][0] = bv.x; acc[i][1] = bv.y; acc[i][2] = bv.z; acc[i][3] = bv.w;
    }

    #pragma unroll
    for (int d = 0; d < D; d++) {
        float4 hv = *reinterpret_cast<const float4*>(&hT[d * TPAD + (ty << 2)]);
        float4 wv = *reinterpret_cast<const float4*>(&Wt[d * TPAD + (tx << 2)]);
        acc[0][0] = fmaf(hv.x, wv.x, acc[0][0]);
        acc[0][1] = fmaf(hv.x, wv.y, acc[0][1]);
        acc[0][2] = fmaf(hv.x, wv.z, acc[0][2]);
        acc[0][3] = fmaf(hv.x, wv.w, acc[0][3]);
        acc[1][0] = fmaf(hv.y, wv.x, acc[1][0]);
        acc[1][1] = fmaf(hv.y, wv.y, acc[1][1]);
        acc[1][2] = fmaf(hv.y, wv.z, acc[1][2]);
        acc[1][3] = fmaf(hv.y, wv.w, acc[1][3]);
        acc[2][0] = fmaf(hv.z, wv.x, acc[2][0]);
        acc[2][1] = fmaf(hv.z, wv.y, acc[2][1]);
        acc[2][2] = fmaf(hv.z, wv.z, acc[2][2]);
        acc[2][3] = fmaf(hv.z, wv.w, acc[2][3]);
        acc[3][0] = fmaf(hv.w, wv.x, acc[3][0]);
        acc[3][1] = fmaf(hv.w, wv.y, acc[3][1]);
        acc[3][2] = fmaf(hv.w, wv.z, acc[3][2]);
        acc[3][3] = fmaf(hv.w, wv.w, acc[3][3]);
    }

    // ---- store ----
    #pragma unroll
    for (int i = 0; i < 4; i++) {
        int n = tile0 + (ty << 2) + i;
        if (n < N) {
            float4 o = make_float4(acc[i][0], acc[i][1], acc[i][2], acc[i][3]);
            *(reinterpret_cast<float4*>(out + (size_t)n * D) + tx) = o;
        }
    }
}

extern "C" void kernel_launch(void* const* d_in, const int* in_sizes, int n_in,
                              void* d_out, int out_size)
{
    const float* x    = (const float*)d_in[0];   // [N, 64]
    const float* W    = (const float*)d_in[1];   // [64, 64]
    const float* bvec = (const float*)d_in[2];   // [64]
    const float* beta = (const float*)d_in[3];   // [1]
    const int*   ei   = (const int*)  d_in[4];   // [2, E]

    int N = in_sizes[0] / D;
    int E = in_sizes[4] / 2;
    float* out = (float*)d_out;

    void *sp = nullptr, *tp = nullptr;
    cudaGetSymbolAddress(&sp, g_s);
    cudaGetSymbolAddress(&tp, g_t);
    size_t bytes = (size_t)N * D * sizeof(float);
    cudaMemsetAsync(sp, 0, bytes);
    cudaMemsetAsync(tp, 0, bytes);

    long long threads = (long long)E * 16;
    int blocks = (int)((threads + 255) / 256);
    edge_kernel<<<blocks, 256>>>(x, ei, beta, E);

    int gblocks = (N + 63) / 64;
    gemm_kernel<<<gblocks, 256>>>((const float*)sp, (const float*)tp, W, bvec, out, N);
}